// round 3
// baseline (speedup 1.0000x reference)
#include <cuda_runtime.h>

// DiffJPEG: per-8x8-block DCT -> quantize/dequantize -> IDCT.
// (32, 3, 512, 512) fp32. 8 threads per 8x8 block (one row each);
// transposes between separable passes done with XOR warp shuffles
// (no shared memory, no barriers).

#define C1 0.4903926402f
#define C2 0.4619397663f
#define C3 0.4157348062f
#define C4 0.3535533906f
#define C5 0.2777851165f
#define C6 0.1913417162f
#define C7 0.0975451610f

__device__ __forceinline__ void dct8(float x[8]) {
    float s0 = x[0] + x[7], s1 = x[1] + x[6], s2 = x[2] + x[5], s3 = x[3] + x[4];
    float d0 = x[0] - x[7], d1 = x[1] - x[6], d2 = x[2] - x[5], d3 = x[3] - x[4];
    float e0 = s0 + s3, e1 = s1 + s2;
    float f0 = s0 - s3, f1 = s1 - s2;
    x[0] = C4 * (e0 + e1);
    x[4] = C4 * (e0 - e1);
    x[2] = C2 * f0 + C6 * f1;
    x[6] = C6 * f0 - C2 * f1;
    x[1] = C1 * d0 + C3 * d1 + C5 * d2 + C7 * d3;
    x[3] = C3 * d0 - C7 * d1 - C1 * d2 - C5 * d3;
    x[5] = C5 * d0 - C1 * d1 + C7 * d2 + C3 * d3;
    x[7] = C7 * d0 - C5 * d1 + C3 * d2 - C1 * d3;
}

__device__ __forceinline__ void idct8(float x[8]) {
    float a = C4 * (x[0] + x[4]);
    float b = C4 * (x[0] - x[4]);
    float e0 = a + C2 * x[2] + C6 * x[6];
    float e3 = a - C2 * x[2] - C6 * x[6];
    float e1 = b + C6 * x[2] - C2 * x[6];
    float e2 = b - C6 * x[2] + C2 * x[6];
    float o0 = C1 * x[1] + C3 * x[3] + C5 * x[5] + C7 * x[7];
    float o1 = C3 * x[1] - C7 * x[3] - C1 * x[5] - C5 * x[7];
    float o2 = C5 * x[1] - C1 * x[3] + C7 * x[5] + C3 * x[7];
    float o3 = C7 * x[1] - C5 * x[3] + C3 * x[5] - C1 * x[7];
    x[0] = e0 + o0;  x[7] = e0 - o0;
    x[1] = e1 + o1;  x[6] = e1 - o1;
    x[2] = e2 + o2;  x[5] = e2 - o2;
    x[3] = e3 + o3;  x[4] = e3 - o3;
}

// Transposed quant table: kQT[r][j] = Q[j][r]; lane r uses row r.
static __device__ const float kQT[64] = {
    16.f, 12.f, 14.f, 14.f, 18.f,  24.f,  49.f,  72.f,
    11.f, 12.f, 13.f, 17.f, 22.f,  35.f,  64.f,  92.f,
    10.f, 14.f, 16.f, 22.f, 37.f,  55.f,  78.f,  95.f,
    16.f, 19.f, 24.f, 29.f, 56.f,  64.f,  87.f,  98.f,
    24.f, 26.f, 40.f, 51.f, 68.f,  81.f, 103.f, 112.f,
    40.f, 58.f, 57.f, 87.f, 109.f,104.f, 121.f, 100.f,
    51.f, 60.f, 69.f, 80.f, 103.f,113.f, 120.f, 103.f,
    61.f, 55.f, 56.f, 62.f, 77.f,  92.f, 101.f,  99.f
};
// Reciprocals, constant-folded at compile time.
static __device__ const float kQTi[64] = {
    1.f/16.f, 1.f/12.f, 1.f/14.f, 1.f/14.f, 1.f/18.f,  1.f/24.f,  1.f/49.f,  1.f/72.f,
    1.f/11.f, 1.f/12.f, 1.f/13.f, 1.f/17.f, 1.f/22.f,  1.f/35.f,  1.f/64.f,  1.f/92.f,
    1.f/10.f, 1.f/14.f, 1.f/16.f, 1.f/22.f, 1.f/37.f,  1.f/55.f,  1.f/78.f,  1.f/95.f,
    1.f/16.f, 1.f/19.f, 1.f/24.f, 1.f/29.f, 1.f/56.f,  1.f/64.f,  1.f/87.f,  1.f/98.f,
    1.f/24.f, 1.f/26.f, 1.f/40.f, 1.f/51.f, 1.f/68.f,  1.f/81.f,  1.f/103.f, 1.f/112.f,
    1.f/40.f, 1.f/58.f, 1.f/57.f, 1.f/87.f, 1.f/109.f, 1.f/104.f, 1.f/121.f, 1.f/100.f,
    1.f/51.f, 1.f/60.f, 1.f/69.f, 1.f/80.f, 1.f/103.f, 1.f/113.f, 1.f/120.f, 1.f/103.f,
    1.f/61.f, 1.f/55.f, 1.f/56.f, 1.f/62.f, 1.f/77.f,  1.f/92.f,  1.f/101.f, 1.f/99.f
};

// 8x8 transpose across 8 lanes via XOR butterfly (12 shfl, no smem).
__device__ __forceinline__ void transpose8(float x[8], int r) {
#pragma unroll
    for (int m = 1; m < 8; m <<= 1) {
        bool hi = (r & m) != 0;
#pragma unroll
        for (int i = 0; i < 8; i++) {
            if ((i & m) == 0) {
                int j = i + m;
                float send = hi ? x[i] : x[j];
                float recv = __shfl_xor_sync(0xffffffffu, send, m);
                if (hi) x[i] = recv; else x[j] = recv;
            }
        }
    }
}

static constexpr int kW = 512;
static constexpr int kNumCtas = 32 * 3 * 64 * 2;   // 12288: CTA = 32 blocks

__global__ __launch_bounds__(256)
void diffjpeg_kernel(const float* __restrict__ in, float* __restrict__ out) {
    int t  = threadIdx.x;
    int r  = t & 7;          // row within 8x8 block
    int bk = t >> 3;         // block-in-CTA 0..31

    unsigned cta = blockIdx.x;
    // 128 CTAs per (image,channel): 64 block-rows x 2 halves of the width
    size_t base = ((size_t)(cta >> 7) << 18)
                + ((size_t)((cta & 127) >> 1) << 12)
                + ((size_t)(cta & 1) << 8);
    size_t off = base + (size_t)r * kW + bk * 8;

    float x[8];
    {
        float4 a = *reinterpret_cast<const float4*>(in + off);
        float4 b = *reinterpret_cast<const float4*>(in + off + 4);
        x[0] = a.x; x[1] = a.y; x[2] = a.z; x[3] = a.w;
        x[4] = b.x; x[5] = b.y; x[6] = b.z; x[7] = b.w;
    }

    // Pass 1: row DCT -> X * D^T
    dct8(x);
    // Transpose (shuffles)
    transpose8(x, r);
    // Pass 2: row DCT -> (D X D^T)^T ; lane r holds Y[:, r]
    dct8(x);

    // Quantize/dequantize: element j needs Q[j][r] = kQT[r][j].
    {
        const float4* qp  = reinterpret_cast<const float4*>(kQT)  + (r << 1);
        const float4* qip = reinterpret_cast<const float4*>(kQTi) + (r << 1);
        float4 q0 = qp[0],  q1 = qp[1];
        float4 i0 = qip[0], i1 = qip[1];
        x[0] = rintf(x[0] * i0.x) * q0.x;
        x[1] = rintf(x[1] * i0.y) * q0.y;
        x[2] = rintf(x[2] * i0.z) * q0.z;
        x[3] = rintf(x[3] * i0.w) * q0.w;
        x[4] = rintf(x[4] * i1.x) * q1.x;
        x[5] = rintf(x[5] * i1.y) * q1.y;
        x[6] = rintf(x[6] * i1.z) * q1.z;
        x[7] = rintf(x[7] * i1.w) * q1.w;
    }

    // Pass 3: row IDCT
    idct8(x);
    // Transpose back
    transpose8(x, r);
    // Pass 4: row IDCT -> rows match output layout
    idct8(x);

    {
        float4 a = make_float4(x[0], x[1], x[2], x[3]);
        float4 b = make_float4(x[4], x[5], x[6], x[7]);
        *reinterpret_cast<float4*>(out + off)     = a;
        *reinterpret_cast<float4*>(out + off + 4) = b;
    }
}

extern "C" void kernel_launch(void* const* d_in, const int* in_sizes, int n_in,
                              void* d_out, int out_size) {
    const float* img = (const float*)d_in[0];
    float* out = (float*)d_out;
    diffjpeg_kernel<<<kNumCtas, 256>>>(img, out);
}

// round 4
// speedup vs baseline: 1.8202x; 1.8202x over previous
#include <cuda_runtime.h>

// DiffJPEG (32,3,512,512) fp32: per-8x8-block DCT -> quant/dequant -> IDCT.
// One thread per 8x8 block, fully register-resident. All butterflies use
// Blackwell packed f32x2 ops (2 columns or 2 rows per 64-bit register).
// Axis flip between separable passes = in-thread register transpose (ALU only).

typedef unsigned long long u64;

__device__ __forceinline__ u64 pk2(float lo, float hi) {
    u64 r; asm("mov.b64 %0, {%1, %2};" : "=l"(r) : "f"(lo), "f"(hi)); return r;
}
__device__ __forceinline__ float plo(u64 a) { return __uint_as_float((unsigned)a); }
__device__ __forceinline__ float phi(u64 a) { return __uint_as_float((unsigned)(a >> 32)); }

__device__ __forceinline__ u64 padd(u64 a, u64 b) {
    u64 r; asm("add.rn.f32x2 %0, %1, %2;" : "=l"(r) : "l"(a), "l"(b)); return r;
}
__device__ __forceinline__ u64 psub(u64 a, u64 b) {
    u64 r; asm("sub.rn.f32x2 %0, %1, %2;" : "=l"(r) : "l"(a), "l"(b)); return r;
}
__device__ __forceinline__ u64 pmul(u64 a, u64 b) {
    u64 r; asm("mul.rn.f32x2 %0, %1, %2;" : "=l"(r) : "l"(a), "l"(b)); return r;
}
__device__ __forceinline__ u64 pfma(u64 a, u64 b, u64 c) {
    u64 r; asm("fma.rn.f32x2 %0, %1, %2, %3;" : "=l"(r) : "l"(a), "l"(b), "l"(c)); return r;
}

#define C1f 0.4903926402f
#define C2f 0.4619397663f
#define C3f 0.4157348062f
#define C4f 0.3535533906f
#define C5f 0.2777851165f
#define C6f 0.1913417162f
#define C7f 0.0975451610f

// Forward 8-point DCT-II on packed pairs.
__device__ __forceinline__ void dct8p(u64& x0, u64& x1, u64& x2, u64& x3,
                                      u64& x4, u64& x5, u64& x6, u64& x7,
                                      const u64* K) {
    u64 s0 = padd(x0, x7), s1 = padd(x1, x6), s2 = padd(x2, x5), s3 = padd(x3, x4);
    u64 d0 = psub(x0, x7), d1 = psub(x1, x6), d2 = psub(x2, x5), d3 = psub(x3, x4);
    u64 e0 = padd(s0, s3), e1 = padd(s1, s2);
    u64 f0 = psub(s0, s3), f1 = psub(s1, s2);
    x0 = pmul(K[4], padd(e0, e1));
    x4 = pmul(K[4], psub(e0, e1));
    x2 = pfma(K[2], f0, pmul(K[6], f1));
    x6 = psub(pmul(K[6], f0), pmul(K[2], f1));
    x1 = pfma(K[1], d0, pfma(K[3], d1, pfma(K[5], d2, pmul(K[7], d3))));
    x3 = psub(pmul(K[3], d0), pfma(K[7], d1, pfma(K[1], d2, pmul(K[5], d3))));
    x5 = psub(pfma(K[5], d0, pfma(K[7], d2, pmul(K[3], d3))), pmul(K[1], d1));
    x7 = psub(pfma(K[7], d0, pmul(K[3], d2)), pfma(K[5], d1, pmul(K[1], d3)));
}

// Inverse 8-point DCT on packed pairs.
__device__ __forceinline__ void idct8p(u64& x0, u64& x1, u64& x2, u64& x3,
                                       u64& x4, u64& x5, u64& x6, u64& x7,
                                       const u64* K) {
    u64 a = pmul(K[4], padd(x0, x4));
    u64 b = pmul(K[4], psub(x0, x4));
    u64 u = pfma(K[2], x2, pmul(K[6], x6));
    u64 v = psub(pmul(K[6], x2), pmul(K[2], x6));
    u64 e0 = padd(a, u), e3 = psub(a, u);
    u64 e1 = padd(b, v), e2 = psub(b, v);
    u64 o0 = pfma(K[1], x1, pfma(K[3], x3, pfma(K[5], x5, pmul(K[7], x7))));
    u64 o1 = psub(pmul(K[3], x1), pfma(K[7], x3, pfma(K[1], x5, pmul(K[5], x7))));
    u64 o2 = psub(pfma(K[5], x1, pfma(K[7], x5, pmul(K[3], x7))), pmul(K[1], x3));
    u64 o3 = psub(pfma(K[7], x1, pmul(K[3], x5)), pfma(K[5], x3, pmul(K[1], x7)));
    x0 = padd(e0, o0);  x7 = psub(e0, o0);
    x1 = padd(e1, o1);  x6 = psub(e1, o1);
    x2 = padd(e2, o2);  x5 = psub(e2, o2);
    x3 = padd(e3, o3);  x4 = psub(e3, o3);
}

// 2x2 element-block transpose across two packed regs.
__device__ __forceinline__ void tr2(u64& x0, u64& x1) {
    u64 y0 = pk2(plo(x0), plo(x1));
    u64 y1 = pk2(phi(x0), phi(x1));
    x0 = y0; x1 = y1;
}

// In-place 8x8 element transpose of A[8][4] packed state.
__device__ __forceinline__ void repack(u64 A[8][4]) {
#pragma unroll
    for (int a = 0; a < 4; a++) {
        tr2(A[2 * a][a], A[2 * a + 1][a]);
#pragma unroll
        for (int b = a + 1; b < 4; b++) {
            u64 p0 = A[2 * a][b], p1 = A[2 * a + 1][b];
            u64 q0 = A[2 * b][a], q1 = A[2 * b + 1][a];
            tr2(p0, p1); tr2(q0, q1);
            A[2 * a][b] = q0; A[2 * a + 1][b] = q1;
            A[2 * b][a] = p0; A[2 * b + 1][a] = p1;
        }
    }
}

// Packed quant tables, indexed [j*4+q] = {Q[2q][j], Q[2q+1][j]}.
static __device__ __constant__ float2 kQv[32] = {
    {16.f,12.f},{14.f,14.f},{18.f,24.f},{49.f,72.f},
    {11.f,12.f},{13.f,17.f},{22.f,35.f},{64.f,92.f},
    {10.f,14.f},{16.f,22.f},{37.f,55.f},{78.f,95.f},
    {16.f,19.f},{24.f,29.f},{56.f,64.f},{87.f,98.f},
    {24.f,26.f},{40.f,51.f},{68.f,81.f},{103.f,112.f},
    {40.f,58.f},{57.f,87.f},{109.f,104.f},{121.f,100.f},
    {51.f,60.f},{69.f,80.f},{103.f,113.f},{120.f,103.f},
    {61.f,55.f},{56.f,62.f},{77.f,92.f},{101.f,99.f}
};
static __device__ __constant__ float2 kQi[32] = {
    {1.f/16,1.f/12},{1.f/14,1.f/14},{1.f/18,1.f/24},{1.f/49,1.f/72},
    {1.f/11,1.f/12},{1.f/13,1.f/17},{1.f/22,1.f/35},{1.f/64,1.f/92},
    {1.f/10,1.f/14},{1.f/16,1.f/22},{1.f/37,1.f/55},{1.f/78,1.f/95},
    {1.f/16,1.f/19},{1.f/24,1.f/29},{1.f/56,1.f/64},{1.f/87,1.f/98},
    {1.f/24,1.f/26},{1.f/40,1.f/51},{1.f/68,1.f/81},{1.f/103,1.f/112},
    {1.f/40,1.f/58},{1.f/57,1.f/87},{1.f/109,1.f/104},{1.f/121,1.f/100},
    {1.f/51,1.f/60},{1.f/69,1.f/80},{1.f/103,1.f/113},{1.f/120,1.f/103},
    {1.f/61,1.f/55},{1.f/56,1.f/62},{1.f/77,1.f/92},{1.f/101,1.f/99}
};

static constexpr int kNumBlocks = 32 * 3 * 64 * 64;   // 393216

__global__ __launch_bounds__(128)
void diffjpeg_kernel(const float* __restrict__ in, float* __restrict__ out) {
    unsigned t = blockIdx.x * 128u + threadIdx.x;

    unsigned bc  = t & 63u;
    unsigned br  = (t >> 6) & 63u;
    unsigned img = t >> 12;
    unsigned off = (img << 18) + (br << 12) + (bc << 3);   // elements

    const float* p = in + off;
    float* qo = out + off;

    // Packed constants (both halves identical).
    u64 K[8];
    K[1] = pk2(C1f, C1f); K[2] = pk2(C2f, C2f); K[3] = pk2(C3f, C3f);
    K[4] = pk2(C4f, C4f); K[5] = pk2(C5f, C5f); K[6] = pk2(C6f, C6f);
    K[7] = pk2(C7f, C7f);
    const u64 MAG = pk2(12582912.0f, 12582912.0f);   // 1.5 * 2^23

    // State: A[r][p] = {x[r][2p], x[r][2p+1]}  (column-pair packing).
    u64 A[8][4];
#pragma unroll
    for (int r = 0; r < 8; r++) {
        ulonglong2 a = *reinterpret_cast<const ulonglong2*>(p + r * 512);
        ulonglong2 b = *reinterpret_cast<const ulonglong2*>(p + r * 512 + 4);
        A[r][0] = a.x; A[r][1] = a.y; A[r][2] = b.x; A[r][3] = b.y;
    }

    // Column DCT (combine over r), 2 columns per call.
#pragma unroll
    for (int c = 0; c < 4; c++)
        dct8p(A[0][c], A[1][c], A[2][c], A[3][c], A[4][c], A[5][c], A[6][c], A[7][c], K);

    repack(A);   // -> row-pair packing: A[j][q] = {Y[2q][j], Y[2q+1][j]}

    // Row DCT (combine over j), 2 rows per call.
#pragma unroll
    for (int c = 0; c < 4; c++)
        dct8p(A[0][c], A[1][c], A[2][c], A[3][c], A[4][c], A[5][c], A[6][c], A[7][c], K);

    // Quantize (RNE via magic constant) and dequantize, fully packed.
#pragma unroll
    for (int j = 0; j < 8; j++) {
#pragma unroll
        for (int q = 0; q < 4; q++) {
            u64 qi = *reinterpret_cast<const u64*>(&kQi[j * 4 + q]);
            u64 qv = *reinterpret_cast<const u64*>(&kQv[j * 4 + q]);
            u64 v = pmul(A[j][q], qi);
            v = padd(v, MAG);
            v = psub(v, MAG);
            A[j][q] = pmul(v, qv);
        }
    }

    // Row IDCT.
#pragma unroll
    for (int c = 0; c < 4; c++)
        idct8p(A[0][c], A[1][c], A[2][c], A[3][c], A[4][c], A[5][c], A[6][c], A[7][c], K);

    repack(A);   // back to column-pair packing

    // Column IDCT.
#pragma unroll
    for (int c = 0; c < 4; c++)
        idct8p(A[0][c], A[1][c], A[2][c], A[3][c], A[4][c], A[5][c], A[6][c], A[7][c], K);

    // Store.
#pragma unroll
    for (int r = 0; r < 8; r++) {
        ulonglong2 a; a.x = A[r][0]; a.y = A[r][1];
        ulonglong2 b; b.x = A[r][2]; b.y = A[r][3];
        *reinterpret_cast<ulonglong2*>(qo + r * 512)     = a;
        *reinterpret_cast<ulonglong2*>(qo + r * 512 + 4) = b;
    }
}

extern "C" void kernel_launch(void* const* d_in, const int* in_sizes, int n_in,
                              void* d_out, int out_size) {
    const float* img = (const float*)d_in[0];
    float* out = (float*)d_out;
    diffjpeg_kernel<<<kNumBlocks / 128, 128>>>(img, out);
}